// round 8
// baseline (speedup 1.0000x reference)
#include <cuda_runtime.h>
#include <cuda_fp16.h>
#include <math.h>
#include <stdint.h>

// Problem constants
#define Bb     32
#define Dd     64
#define Kk     512
#define DHW    262144        // D*H*W
#define Nn     131072        // B*H*W
#define EPSf   1e-5f
#define NTILES 1024          // 128-row tiles
#define GRID_P 148           // persistent CTAs

// ---------------------------------------------------------------------------
// Helpers
// ---------------------------------------------------------------------------
__device__ __forceinline__ uint32_t smem_to_u32(const void* p) {
    uint32_t a;
    asm("{ .reg .u64 t; cvta.to.shared.u64 t, %1; cvt.u32.u64 %0, t; }" : "=r"(a) : "l"(p));
    return a;
}
__device__ __forceinline__ uint32_t pack_h2(float a, float b) {
    __half2 h = __floats2half2_rn(a, b);
    return *(uint32_t*)&h;
}
// D = A(16x16 f16, row) * B(16x8 f16, col) + D, fp32 accum
__device__ __forceinline__ void mma_f16(float* c, const uint32_t* a, uint32_t b0, uint32_t b1) {
    asm volatile("mma.sync.aligned.m16n8k16.row.col.f32.f16.f16.f32 "
        "{%0,%1,%2,%3}, {%4,%5,%6,%7}, {%8,%9}, {%0,%1,%2,%3};"
        : "+f"(c[0]), "+f"(c[1]), "+f"(c[2]), "+f"(c[3])
        : "r"(a[0]), "r"(a[1]), "r"(a[2]), "r"(a[3]), "r"(b0), "r"(b1));
}
#define CP_ASYNC16(s, g) asm volatile("cp.async.cg.shared.global [%0], [%1], 16;" :: "r"(s), "l"(g))
#define CP_COMMIT()      asm volatile("cp.async.commit_group;" ::: "memory")
#define CP_WAIT0()       asm volatile("cp.async.wait_group 0;" ::: "memory")

// ---------------------------------------------------------------------------
// Scratch
// ---------------------------------------------------------------------------
__device__ float d_ec[Kk];                 // ||e_k||^2 (fp32)
__device__ int   d_counts[Kk];
__device__ float d_sums[Dd * Kk];          // embed sums [D][K]
__device__ float d_scale[Kk];
// codebook hi-fp16 mma-fragments: [ntile(64)][kstep(4)][lane(32)] -> {b0hi, b1hi}
__device__ uint2 g_fragh[8192];

// ---------------------------------------------------------------------------
// Kernel A: zero sums/counts, ||e_k||^2, fp16 codebook fragments
// ---------------------------------------------------------------------------
__global__ void prep_kernel(const float* __restrict__ emb) {
    int t = threadIdx.x;
    int i = blockIdx.x * 512 + t;          // 0..32767
    d_sums[i] = 0.f;

    if (i < 8192) {   // fragment entry i
        int lane = i & 31;
        int ks   = (i >> 5) & 3;
        int nt   = i >> 7;                 // 0..63
        int code = nt * 8 + (lane >> 2);
        int k0   = ks * 16 + (lane & 3) * 2;
        const float* er = emb + code * 64 + k0;
        uint2 f;
        f.x = pack_h2(__ldg(er),     __ldg(er + 1));
        f.y = pack_h2(__ldg(er + 8), __ldg(er + 9));
        g_fragh[i] = f;
    }

    if (blockIdx.x == 0) {
        d_counts[t] = 0;
        const float4* r = (const float4*)(emb + (t << 6));
        float s = 0.f;
#pragma unroll
        for (int j = 0; j < 16; j++) {
            float4 v = __ldg(r + j);
            s += v.x * v.x + v.y * v.y + v.z * v.z + v.w * v.w;
        }
        d_ec[t] = s;
    }
}

// ---------------------------------------------------------------------------
// SMEM layout (bytes)
// ---------------------------------------------------------------------------
#define XLD       132
#define SM_XB     0           // x tile [64 d][132 f32]          33792
#define SM_FRAGH  33792       // hi fragments                     65536
#define SM_SCORE  99328       // fp16 scores [128 r][512 k]      131072  (reused as sq)
#define SM_ECH    230400      // ec fp16 [512]                     1024
#define SM_SIDX   231424      // winner idx [128 i32]               512
#define SM_SR     231936      // S_r fp16 [128]                     256
#define SM_TOTAL  232192

// ---------------------------------------------------------------------------
// Kernel B: persistent 1-term fp16 MMA filter + exact fp32 refine.
//   148 CTAs x 512 threads. Warp = 32 rows x 128 codes.
// ---------------------------------------------------------------------------
__global__ __launch_bounds__(512, 1)
void assign_kernel(const float* __restrict__ x,
                   const float* __restrict__ emb,
                   float* __restrict__ q) {
    extern __shared__ char smem[];
    uint32_t sb = smem_to_u32(smem);
    int tid = threadIdx.x;
    int wid = tid >> 5;
    int lid = tid & 31;
    int grp = lid >> 2;        // 0..7
    int tig = lid & 3;         // 0..3
    int qtr = wid & 3;         // code quarter
    int rws = wid >> 2;        // row set (0..3)

    float* sx   = (float*)(smem + SM_XB);
    int*   sidx = (int*)(smem + SM_SIDX);
    float* sq   = (float*)(smem + SM_SCORE);     // union with scores

    // ---- prologue: fragments + ec_h + first x tile ----
#pragma unroll
    for (int jj = 0; jj < 8; jj++) {
        int i = tid + jj * 512;
        CP_ASYNC16(sb + SM_FRAGH + i * 16, (const char*)g_fragh + i * 16);
    }
    {
        const float* xb = x + (size_t)(blockIdx.x >> 5) * DHW + ((blockIdx.x & 31) << 7);
#pragma unroll
        for (int jj = 0; jj < 4; jj++) {
            int i = tid + jj * 512;
            int d = i >> 5, r4 = (i & 31) << 2;
            CP_ASYNC16(sb + SM_XB + (d * XLD + r4) * 4, (const char*)(xb + (d << 12) + r4));
        }
    }
    if (tid < 256)
        *(uint32_t*)(smem + SM_ECH + tid * 4) = pack_h2(d_ec[2 * tid], d_ec[2 * tid + 1]);
    CP_COMMIT();
    CP_WAIT0();
    __syncthreads();

    // ---- persistent tile loop ----
    int j = 0;
    for (int t = blockIdx.x; t < NTILES; t += GRID_P, j++) {
        int b   = t >> 5;
        int hw0 = (t & 31) << 7;

        if (j > 0) {   // blocking x load (sx freed by previous end-of-tile sync)
            const float* xb = x + (size_t)b * DHW + hw0;
#pragma unroll
            for (int jj = 0; jj < 4; jj++) {
                int i = tid + jj * 512;
                int d = i >> 5, r4 = (i & 31) << 2;
                CP_ASYNC16(sb + SM_XB + (d * XLD + r4) * 4, (const char*)(xb + (d << 12) + r4));
            }
            CP_COMMIT();
            CP_WAIT0();
            __syncthreads();
        }

        // ---- A fragments (hi only) + per-row sum|x| ----
        uint32_t Ahi[32];
        float sabs[4] = {0.f, 0.f, 0.f, 0.f};
#pragma unroll
        for (int mt = 0; mt < 2; mt++) {
            int rb = rws * 32 + mt * 16 + grp;
#pragma unroll
            for (int ks = 0; ks < 4; ks++) {
                int kb = ks * 16 + tig * 2;
                float v00 = sx[kb * XLD + rb],           v01 = sx[(kb + 1) * XLD + rb];
                float v10 = sx[kb * XLD + rb + 8],       v11 = sx[(kb + 1) * XLD + rb + 8];
                float v20 = sx[(kb + 8) * XLD + rb],     v21 = sx[(kb + 9) * XLD + rb];
                float v30 = sx[(kb + 8) * XLD + rb + 8], v31 = sx[(kb + 9) * XLD + rb + 8];
                int o = mt * 16 + ks * 4;
                Ahi[o + 0] = pack_h2(v00, v01);
                Ahi[o + 1] = pack_h2(v10, v11);
                Ahi[o + 2] = pack_h2(v20, v21);
                Ahi[o + 3] = pack_h2(v30, v31);
                sabs[mt * 2]     += fabsf(v00) + fabsf(v01) + fabsf(v20) + fabsf(v21);
                sabs[mt * 2 + 1] += fabsf(v10) + fabsf(v11) + fabsf(v30) + fabsf(v31);
            }
        }
        // quad-reduce row |x| sums; qtr0 tig0 stores S_r (fp16)
#pragma unroll
        for (int o = 1; o <= 2; o <<= 1) {
#pragma unroll
            for (int v = 0; v < 4; v++) sabs[v] += __shfl_xor_sync(0xffffffffu, sabs[v], o);
        }
        if (qtr == 0 && tig == 0) {
            int rb = rws * 32 + grp;
            ((__half*)(smem + SM_SR))[rb]      = __float2half_rn(sabs[0]);
            ((__half*)(smem + SM_SR))[rb + 8]  = __float2half_rn(sabs[1]);
            ((__half*)(smem + SM_SR))[rb + 16] = __float2half_rn(sabs[2]);
            ((__half*)(smem + SM_SR))[rb + 24] = __float2half_rn(sabs[3]);
        }

        // ---- 1-term MMA + approx score write (fp16) ----
        int rl0 = rws * 32 + grp;
#pragma unroll 2
        for (int np = 0; np < 8; np++) {
            int ntA = (qtr << 4) + 2 * np;
            float acc[4][4] = {{0.f,0.f,0.f,0.f},{0.f,0.f,0.f,0.f},
                               {0.f,0.f,0.f,0.f},{0.f,0.f,0.f,0.f}};
#pragma unroll
            for (int ks = 0; ks < 4; ks++) {
                uint32_t a0 = sb + SM_FRAGH + (((ntA << 2) + ks) * 32 + lid) * 8;
                uint2 bA, bB;
                asm volatile("ld.shared.v2.b32 {%0,%1}, [%2];"
                    : "=r"(bA.x), "=r"(bA.y) : "r"(a0));
                asm volatile("ld.shared.v2.b32 {%0,%1}, [%2];"
                    : "=r"(bB.x), "=r"(bB.y) : "r"(a0 + 1024));
                mma_f16(acc[0], &Ahi[ks * 4],      bA.x, bA.y);
                mma_f16(acc[1], &Ahi[ks * 4],      bB.x, bB.y);
                mma_f16(acc[2], &Ahi[16 + ks * 4], bA.x, bA.y);
                mma_f16(acc[3], &Ahi[16 + ks * 4], bB.x, bB.y);
            }
            int base0 = ntA * 8 + 2 * tig;
            __half2 eh0 = *(__half2*)(smem + SM_ECH + base0 * 2);
            __half2 eh1 = *(__half2*)(smem + SM_ECH + (base0 + 8) * 2);
            float2 e0 = __half22float2(eh0), e1 = __half22float2(eh1);
            // rows rl0, rl0+8 (mt0) and rl0+16, rl0+24 (mt1)
#pragma unroll
            for (int mt = 0; mt < 2; mt++) {
                int ra = rl0 + mt * 16, rb2 = ra + 8;
                float* cA = acc[mt * 2];      // codes base0, base0+1
                float* cB = acc[mt * 2 + 1];  // codes base0+8, base0+9
                *(uint32_t*)(smem + SM_SCORE + ra  * 1024 + base0 * 2) =
                    pack_h2(fmaf(cA[0], -2.f, e0.x), fmaf(cA[1], -2.f, e0.y));
                *(uint32_t*)(smem + SM_SCORE + rb2 * 1024 + base0 * 2) =
                    pack_h2(fmaf(cA[2], -2.f, e0.x), fmaf(cA[3], -2.f, e0.y));
                *(uint32_t*)(smem + SM_SCORE + ra  * 1024 + (base0 + 8) * 2) =
                    pack_h2(fmaf(cB[0], -2.f, e1.x), fmaf(cB[1], -2.f, e1.y));
                *(uint32_t*)(smem + SM_SCORE + rb2 * 1024 + (base0 + 8) * 2) =
                    pack_h2(fmaf(cB[2], -2.f, e1.x), fmaf(cB[3], -2.f, e1.y));
            }
        }
        __syncthreads();

        // ---- scan + exact refine: 4 threads per row, 128 codes each ----
        {
            int r = tid >> 2, sub = tid & 3;
            const uint4* srow = (const uint4*)(smem + SM_SCORE + r * 1024 + sub * 256);
            float mn = 3.4e38f;
#pragma unroll
            for (int i = 0; i < 16; i++) {
                uint4 v = srow[i];
                float2 f0 = __half22float2(*(__half2*)&v.x);
                float2 f1 = __half22float2(*(__half2*)&v.y);
                float2 f2 = __half22float2(*(__half2*)&v.z);
                float2 f3 = __half22float2(*(__half2*)&v.w);
                mn = fminf(mn, fminf(fminf(fminf(f0.x, f0.y), fminf(f1.x, f1.y)),
                                     fminf(fminf(f2.x, f2.y), fminf(f3.x, f3.y))));
            }
#pragma unroll
            for (int o = 1; o <= 2; o <<= 1)
                mn = fminf(mn, __shfl_xor_sync(0xffffffffu, mn, o));

            float Sr = __half2float(((const __half*)(smem + SM_SR))[r]) * 1.01f;
            float T  = mn + 3.4e-3f * Sr + 0.002f * fabsf(mn) + 0.25f;

            // candidate sweep + exact fp32 rescore
            float bE = 3.4e38f;
            int   bK = 1 << 20;
            const float* sxr = sx + r;
#pragma unroll 4
            for (int i = 0; i < 16; i++) {
                uint4 v = srow[i];
                float fs[8];
                {
                    float2 f0 = __half22float2(*(__half2*)&v.x);
                    float2 f1 = __half22float2(*(__half2*)&v.y);
                    float2 f2 = __half22float2(*(__half2*)&v.z);
                    float2 f3 = __half22float2(*(__half2*)&v.w);
                    fs[0]=f0.x; fs[1]=f0.y; fs[2]=f1.x; fs[3]=f1.y;
                    fs[4]=f2.x; fs[5]=f2.y; fs[6]=f3.x; fs[7]=f3.y;
                }
#pragma unroll
                for (int o = 0; o < 8; o++) {
                    if (fs[o] <= T) {
                        int k = sub * 128 + i * 8 + o;
                        const float4* ew = (const float4*)(emb + k * 64);
                        float a0 = 0.f, a1 = 0.f, a2 = 0.f, a3 = 0.f;
#pragma unroll
                        for (int jj = 0; jj < 16; jj++) {
                            float4 e4 = __ldg(ew + jj);
                            a0 = fmaf(sxr[(4 * jj)     * XLD], e4.x, a0);
                            a1 = fmaf(sxr[(4 * jj + 1) * XLD], e4.y, a1);
                            a2 = fmaf(sxr[(4 * jj + 2) * XLD], e4.z, a2);
                            a3 = fmaf(sxr[(4 * jj + 3) * XLD], e4.w, a3);
                        }
                        float ex = __ldg(&d_ec[k]) - 2.f * ((a0 + a1) + (a2 + a3));
                        if (ex < bE || (ex == bE && k < bK)) { bE = ex; bK = k; }
                    }
                }
            }
#pragma unroll
            for (int o = 1; o <= 2; o <<= 1) {
                float oe = __shfl_xor_sync(0xffffffffu, bE, o);
                int   ok = __shfl_xor_sync(0xffffffffu, bK, o);
                if (oe < bE || (oe == bE && ok < bK)) { bE = oe; bK = ok; }
            }
            if (sub == 0) {
                sidx[r] = bK;
                atomicAdd(&d_counts[bK], 1);
            }
        }
        __syncthreads();

        // ---- epilogue: coalesced q via staging (reuses score region), sums ----
        float* qb = q + (size_t)b * DHW + hw0;
#pragma unroll
        for (int pass = 0; pass < 2; pass++) {
#pragma unroll
            for (int it = 0; it < 2; it++) {
                int item = tid + it * 512;          // 0..1023
                int r = item >> 3, c = item & 7;
                int ki = sidx[r];
                float4 ev = __ldg((const float4*)(emb + ki * 64 + pass * 32 + c * 4));
                float* sp = sq + r * 37 + c * 4;
                sp[0] = ev.x; sp[1] = ev.y; sp[2] = ev.z; sp[3] = ev.w;
            }
            __syncthreads();
#pragma unroll
            for (int it = 0; it < 2; it++) {
                int item = tid + it * 512;
                int dd = item >> 5, g = item & 31;
                int d  = pass * 32 + dd;
                float4 ov;
                ov.x = sq[(4 * g)     * 37 + dd];
                ov.y = sq[(4 * g + 1) * 37 + dd];
                ov.z = sq[(4 * g + 2) * 37 + dd];
                ov.w = sq[(4 * g + 3) * 37 + dd];
                ((float4*)(qb + (d << 12)))[g] = ov;
                int k0 = sidx[4 * g], k1 = sidx[4 * g + 1];
                int k2 = sidx[4 * g + 2], k3 = sidx[4 * g + 3];
                const float* xr = sx + d * XLD + 4 * g;
                atomicAdd(&d_sums[(d << 9) + k0], xr[0]);
                atomicAdd(&d_sums[(d << 9) + k1], xr[1]);
                atomicAdd(&d_sums[(d << 9) + k2], xr[2]);
                atomicAdd(&d_sums[(d << 9) + k3], xr[3]);
            }
            __syncthreads();
        }
    }
}

// ---------------------------------------------------------------------------
// Kernel C: counts EMA -> norm factor (single CTA)
// ---------------------------------------------------------------------------
__device__ __forceinline__ int decode_scalar_int(const int* p) {
    int v = *p;
    if (v >= 0 && v < 1000000) return v;
    return (int)__int_as_float(v);
}

__global__ void norm_kernel(const float* __restrict__ ema_c,
                            const int* __restrict__ counter) {
    __shared__ float wsum[16];
    __shared__ float tot;
    int k = threadIdx.x;

    int   cnt  = decode_scalar_int(counter) + 1;
    float bias = 1.f - (float)pow(0.99, (double)cnt);

    float avg_c = (ema_c[k] * 0.99f + (float)d_counts[k] * 0.01f) / bias;

    float s = avg_c;
#pragma unroll
    for (int o = 16; o > 0; o >>= 1) s += __shfl_xor_sync(0xffffffffu, s, o);
    if ((k & 31) == 0) wsum[k >> 5] = s;
    __syncthreads();
    if (k < 32) {
        float t = (k < 16) ? wsum[k] : 0.f;
#pragma unroll
        for (int o = 8; o > 0; o >>= 1) t += __shfl_xor_sync(0xffffffffu, t, o);
        if (k == 0) tot = t;
    }
    __syncthreads();
    float nn   = tot;
    float norm = (avg_c + EPSf) / (nn + Kk * EPSf) * nn;
    d_scale[k] = 1.f / (bias * norm);
}

// ---------------------------------------------------------------------------
// Kernel D: emit new_weight [K, D]
// ---------------------------------------------------------------------------
__global__ __launch_bounds__(256)
void weight_kernel(const float* __restrict__ ema_e,
                   const float* __restrict__ emb,
                   const int* __restrict__ training,
                   float* __restrict__ w) {
    int j = blockIdx.x * 256 + threadIdx.x;    // over [D, K]
    int d = j >> 9;
    int k = j & 511;

    int tr = decode_scalar_int(training);
    if (tr != 0) {
        float nhe = ema_e[j] * 0.99f + d_sums[j] * 0.01f;
        w[(k << 6) + d] = nhe * d_scale[k];
    } else {
        w[(k << 6) + d] = emb[(k << 6) + d];
    }
}

// ---------------------------------------------------------------------------
extern "C" void kernel_launch(void* const* d_in, const int* in_sizes, int n_in,
                              void* d_out, int out_size) {
    const float* x        = (const float*)d_in[0];
    const float* emb      = (const float*)d_in[1];
    const float* ema_c    = (const float*)d_in[2];
    const float* ema_e    = (const float*)d_in[3];
    const int*   counter  = (const int*)d_in[4];
    const int*   training = (const int*)d_in[5];

    float* out = (float*)d_out;
    float* q   = out;                          // [B, D, H, W]
    float* w   = out + (size_t)Bb * DHW;       // [K, D]

    cudaFuncSetAttribute(assign_kernel, cudaFuncAttributeMaxDynamicSharedMemorySize, SM_TOTAL);

    prep_kernel  <<<64,     512>>>(emb);
    assign_kernel<<<GRID_P, 512, SM_TOTAL>>>(x, emb, q);
    norm_kernel  <<<1,      Kk>>>(ema_c, counter);
    weight_kernel<<<Dd * Kk / 256, 256>>>(ema_e, emb, training, w);
}